// round 4
// baseline (speedup 1.0000x reference)
#include <cuda_runtime.h>
#include <cuda_bf16.h>
#include <cstdint>

#define NPTS     32768
#define KCODES   1024
#define DDIM     256
#define HWSZ     1024
#define DHW      (DDIM*HWSZ)
#define HALF_OUT 8388608
#define NT       128           // codes per tile
#define NTILES   (KCODES/NT)   // 8
#define CMAXC    32            // candidate cap per point

typedef unsigned int u32;
typedef unsigned short u16;

// Scratch (static __device__ — no allocations)
__device__ float g_xx[NPTS];
__device__ float g_cc[KCODES];
__device__ int   g_idx[NPTS];
__device__ u16   g_cand[NPTS * CMAXC];
__device__ u32   g_ccnt[NPTS];

// Smem layout (dynamic): A [128 x 264 bf16], B [128 x 264 bf16] (B region
// reused as dist [128 x 129 fp32] after each tile's MMAs complete).
#define ASTRIDE 264            // bf16 elems per A/B row (132 words -> 4-bank shift)
#define DSTRIDE 129            // fp32 elems per dist row (1-bank shift, cf-free scan)
#define S_A 0
#define S_B (128 * ASTRIDE * 2)          // 67584
#define SMEM_TOTAL (2 * 128 * ASTRIDE * 2)   // 135168

// m16n8k16 row.col f32.bf16.bf16.f32 (plain PTX — works on sm_103 non-'a')
__device__ __forceinline__ void mma_bf16(float* c, const u32* a, u32 b0, u32 b1) {
    asm volatile(
        "mma.sync.aligned.m16n8k16.row.col.f32.bf16.bf16.f32 "
        "{%0,%1,%2,%3}, {%4,%5,%6,%7}, {%8,%9}, {%0,%1,%2,%3};"
        : "+f"(c[0]), "+f"(c[1]), "+f"(c[2]), "+f"(c[3])
        : "r"(a[0]), "r"(a[1]), "r"(a[2]), "r"(a[3]), "r"(b0), "r"(b1));
}

// ---------------------------------------------------------------------------
// prep: blocks 0..3 -> cc[k]; blocks 4..131 -> xx[n]. Numerics pinned (R1).
// ---------------------------------------------------------------------------
__global__ void prep_kernel(const float* __restrict__ z, const float* __restrict__ cb) {
    int blk = blockIdx.x, tid = threadIdx.x;
    if (blk < 4) {
        int k = blk * 256 + tid;
        const float* row = cb + (size_t)k * DDIM;
        float s = 0.0f;
        for (int d = 0; d < DDIM; ++d) {
            float v = row[d];
            s = __fadd_rn(s, __fmul_rn(v, v));
        }
        g_cc[k] = s;
    } else {
        int n = (blk - 4) * 256 + tid;
        int b = n >> 10, hw = n & 1023;
        const float* base = z + (size_t)b * DHW + hw;
        float s = 0.0f;
        for (int d = 0; d < DDIM; ++d) {
            float v = base[(size_t)d * HWSZ];
            s = __fadd_rn(s, __fmul_rn(v, v));
        }
        g_xx[n] = s;
    }
}

// ---------------------------------------------------------------------------
// Pass 1: bf16 HMMA GEMM (128 pts x 1024 codes x 256) + streaming margin-
// superset candidate collection. 256 threads (8 warps), warp tile 32x64.
// ---------------------------------------------------------------------------
__global__ void __launch_bounds__(256, 1)
pass1_kernel(const float* __restrict__ z, const float* __restrict__ cb) {
    extern __shared__ char smem[];
    u16* As = (u16*)(smem + S_A);
    u16* Bs = (u16*)(smem + S_B);
    const u32* Aw = (const u32*)(smem + S_A);
    const u32* Bw = (const u32*)(smem + S_B);
    float* distS = (float*)(smem + S_B);
    __shared__ float red[256];

    const int tid  = threadIdx.x;
    const int wid  = tid >> 5;
    const int lane = tid & 31;
    const int gid  = lane >> 2;        // groupID (row within fragment)
    const int qid  = lane & 3;         // thread-in-group (k/col pairs)
    const int m0 = (wid & 3) * 32;     // warp m-offset (points)
    const int n0 = (wid >> 2) * 64;    // warp n-offset (codes)

    // cmax = sqrt(max_k cc[k])
    {
        float m = 0.0f;
        for (int k = tid; k < KCODES; k += 256) m = fmaxf(m, g_cc[k]);
        red[tid] = m;
        __syncthreads();
        if (tid < 32) {
            float v = red[tid];
            #pragma unroll
            for (int j = 1; j < 8; ++j) v = fmaxf(v, red[tid + 32 * j]);
            #pragma unroll
            for (int o = 16; o; o >>= 1) v = fmaxf(v, __shfl_xor_sync(0xFFFFFFFF, v, o));
            if (tid == 0) red[0] = v;
        }
        __syncthreads();
    }
    const float cmax = sqrtf(red[0]);

    // Stage A once: As[p][d] = bf16(z[b, d, hw0+p]).  Coalesced gmem reads.
    const int p0 = blockIdx.x * 128;
    const int b = p0 >> 10, hw0 = p0 & 1023;
    const float* zb = z + (size_t)b * DHW + hw0;
    #pragma unroll 4
    for (int idx = tid; idx < 128 * 256; idx += 256) {
        int d = idx >> 7, p = idx & 127;
        __nv_bfloat16 h = __float2bfloat16_rn(zb[(size_t)d * HWSZ + p]);
        As[p * ASTRIDE + d] = __bfloat16_as_ushort(h);
    }

    // Per-point argmin state (threads 0..127 own points)
    const int myp = tid;               // valid when tid < 128
    const int myn = p0 + myp;
    float xxn = 0.0f, margin2 = 0.0f;
    if (tid < 128) {
        xxn = g_xx[myn];
        margin2 = 2.0f * (0.021f * sqrtf(xxn) * cmax + 3e-4f);
    }
    float bmin = 3.0e38f, thr = 3.0e38f;
    int cnt = 0;

    for (int t = 0; t < NTILES; ++t) {
        __syncthreads();   // prior scan done -> safe to overwrite B/dist region
        const int k0t = t * NT;
        // Stage B tile: Bs[k][d] = bf16(cb[k0t+k][d]). float4 reads, 8B stores.
        #pragma unroll 4
        for (int idx = tid; idx < 128 * 64; idx += 256) {
            int k = idx >> 6, d4 = (idx & 63) << 2;
            float4 v = *reinterpret_cast<const float4*>(cb + (size_t)(k0t + k) * DDIM + d4);
            u32 lo = (u32)__bfloat16_as_ushort(__float2bfloat16_rn(v.x))
                   | ((u32)__bfloat16_as_ushort(__float2bfloat16_rn(v.y)) << 16);
            u32 hi = (u32)__bfloat16_as_ushort(__float2bfloat16_rn(v.z))
                   | ((u32)__bfloat16_as_ushort(__float2bfloat16_rn(v.w)) << 16);
            *(uint2*)(&Bs[k * ASTRIDE + d4]) = make_uint2(lo, hi);
        }
        __syncthreads();

        // MMA: warp tile 32x64 = 2 m16 x 8 n8, K = 256 in 16 k16-steps.
        float acc[2][8][4];
        #pragma unroll
        for (int mt = 0; mt < 2; ++mt)
            #pragma unroll
            for (int nt = 0; nt < 8; ++nt)
                #pragma unroll
                for (int r = 0; r < 4; ++r) acc[mt][nt][r] = 0.0f;

        #pragma unroll
        for (int ks = 0; ks < 16; ++ks) {
            const int kw = ks * 8 + qid;   // word col base: (ks*16 + qid*2)/2
            u32 a[2][4];
            #pragma unroll
            for (int mt = 0; mt < 2; ++mt) {
                int rA = m0 + mt * 16 + gid;
                a[mt][0] = Aw[rA * 132 + kw];
                a[mt][1] = Aw[(rA + 8) * 132 + kw];
                a[mt][2] = Aw[rA * 132 + kw + 4];
                a[mt][3] = Aw[(rA + 8) * 132 + kw + 4];
            }
            #pragma unroll
            for (int nt = 0; nt < 8; ++nt) {
                int cB = n0 + nt * 8 + gid;
                u32 b0 = Bw[cB * 132 + kw];
                u32 b1 = Bw[cB * 132 + kw + 4];
                mma_bf16(acc[0][nt], a[0], b0, b1);
                mma_bf16(acc[1][nt], a[1], b0, b1);
            }
        }
        __syncthreads();   // all warps done reading Bs -> reuse region as dist

        // Spill dot products to dist smem (row = point, col = code-in-tile)
        #pragma unroll
        for (int mt = 0; mt < 2; ++mt) {
            #pragma unroll
            for (int nt = 0; nt < 8; ++nt) {
                int r = m0 + mt * 16 + gid;
                int c = n0 + nt * 8 + qid * 2;
                distS[r * DSTRIDE + c]           = acc[mt][nt][0];
                distS[r * DSTRIDE + c + 1]       = acc[mt][nt][1];
                distS[(r + 8) * DSTRIDE + c]     = acc[mt][nt][2];
                distS[(r + 8) * DSTRIDE + c + 1] = acc[mt][nt][3];
            }
        }
        __syncthreads();

        // Scan: owner thread streams its 128 code distances (conflict-free)
        if (tid < 128) {
            const float* row = distS + myp * DSTRIDE;
            #pragma unroll 4
            for (int c = 0; c < NT; ++c) {
                float m = row[c];
                int k = k0t + c;
                float dd = (xxn + __ldg(&g_cc[k])) - 2.0f * m;
                if (dd <= thr) {
                    if (cnt < CMAXC) g_cand[(size_t)myn * CMAXC + cnt] = (u16)k;
                    cnt++;
                    if (dd < bmin) { bmin = dd; thr = dd + margin2; }
                }
            }
        }
    }
    if (tid < 128) g_ccnt[myn] = (u32)cnt;
}

// ---------------------------------------------------------------------------
// Pass 2: exact reference-ordered recompute on candidates. One sequential
// fp32 FMA chain over d=0..255 per (point,code) — bitwise = reference (R1/R2
// proven). Tie-break: lowest k among equal dd (matches jnp.argmin).
// ---------------------------------------------------------------------------
__global__ void __launch_bounds__(256)
exact_kernel(const float* __restrict__ z, const float* __restrict__ cb) {
    int n = blockIdx.x * 256 + threadIdx.x;
    int b = n >> 10, hw = n & 1023;
    const float* xb = z + (size_t)b * DHW + hw;
    float xxn = g_xx[n];
    u32 cnt = g_ccnt[n];
    float best = 3.0e38f;
    int bk = 0x7FFFFFFF;

    if (cnt <= CMAXC) {
        for (u32 i = 0; i < cnt; ++i) {
            int k = g_cand[(size_t)n * CMAXC + i];
            const float* c = cb + (size_t)k * DDIM;
            float m = 0.0f;
            #pragma unroll 8
            for (int d = 0; d < DDIM; ++d)
                m = __fmaf_rn(xb[(size_t)d * HWSZ], c[d], m);
            float t1 = __fadd_rn(xxn, g_cc[k]);
            float dd = __fadd_rn(t1, -(2.0f * m));
            if (dd < best || (dd == best && k < bk)) { best = dd; bk = k; }
        }
    } else {  // overflow fallback: full exact scan (rare)
        for (int k = 0; k < KCODES; ++k) {
            const float* c = cb + (size_t)k * DDIM;
            float m = 0.0f;
            #pragma unroll 8
            for (int d = 0; d < DDIM; ++d)
                m = __fmaf_rn(xb[(size_t)d * HWSZ], c[d], m);
            float t1 = __fadd_rn(xxn, g_cc[k]);
            float dd = __fadd_rn(t1, -(2.0f * m));
            if (dd < best) { best = dd; bk = k; }
        }
    }
    g_idx[n] = bk;
}

// ---------------------------------------------------------------------------
// Gather + straight-through outputs (unchanged, 19us).
// ---------------------------------------------------------------------------
#define GPTS 32
__global__ __launch_bounds__(256)
void gather_kernel(const float* __restrict__ z,
                   const float* __restrict__ cb,
                   float* __restrict__ out) {
    __shared__ float tile[GPTS][DDIM + 1];
    __shared__ int sidx[GPTS];

    const int tid = threadIdx.x;
    const int p0 = blockIdx.x * GPTS;
    const int b = p0 >> 10;
    const int hw0 = p0 & 1023;

    if (tid < GPTS) sidx[tid] = g_idx[p0 + tid];
    __syncthreads();

    #pragma unroll
    for (int r = 0; r < 8; ++r) {
        int lin = tid + r * 256;
        int p = lin >> 6;
        int d4 = (lin & 63) << 2;
        float4 v = *reinterpret_cast<const float4*>(cb + (size_t)sidx[p] * DDIM + d4);
        tile[p][d4 + 0] = v.x;
        tile[p][d4 + 1] = v.y;
        tile[p][d4 + 2] = v.z;
        tile[p][d4 + 3] = v.w;
    }
    __syncthreads();

    const float* zb = z + (size_t)b * DHW + hw0;
    float* o1 = out + (size_t)b * DHW + hw0;
    const int p = tid & 31;
    const int dchunk = tid >> 5;

    #pragma unroll
    for (int dd = 0; dd < DDIM; dd += 8) {
        int d = dd + dchunk;
        size_t off = (size_t)d * HWSZ + p;
        float x = zb[off];
        float q = tile[p][d];
        float t = __fadd_rn(q, -x);
        o1[off]            = __fadd_rn(x, t);
        o1[off + HALF_OUT] = q;
    }
}

// ---------------------------------------------------------------------------
extern "C" void kernel_launch(void* const* d_in, const int* in_sizes, int n_in,
                              void* d_out, int out_size) {
    const float* z  = (const float*)d_in[0];   // z_e_x  [32,256,32,32]
    const float* cb = (const float*)d_in[1];   // codebook [1024,256]
    float* out = (float*)d_out;                // [2, 32,256,32,32]

    static int smem_set = 0;
    if (!smem_set) {
        cudaFuncSetAttribute(pass1_kernel,
                             cudaFuncAttributeMaxDynamicSharedMemorySize, SMEM_TOTAL);
        smem_set = 1;
    }

    prep_kernel<<<132, 256>>>(z, cb);
    pass1_kernel<<<NPTS / 128, 256, SMEM_TOTAL>>>(z, cb);
    exact_kernel<<<NPTS / 256, 256>>>(z, cb);
    gather_kernel<<<NPTS / GPTS, 256>>>(z, cb, out);
}